// round 6
// baseline (speedup 1.0000x reference)
#include <cuda_runtime.h>
#include <math.h>

#define B_  32
#define N_  1024
#define CD_ 896
#define GD_ 384
#define HD_ 256
#define OD_ 1280

// ---------------- scratch (device globals; no allocation allowed) ------------
__device__ float g_Q[B_ * N_ * HD_];     // 32 MB
__device__ float g_K[B_ * N_ * HD_];     // 32 MB
__device__ float g_V[B_ * N_ * HD_];     // 32 MB
__device__ float g_att[B_ * N_ * HD_];   // 32 MB (attended)
__device__ float g_cpool[B_ * CD_];
__device__ float g_gpool[B_ * HD_];
__device__ float g_comb[B_ * OD_];
__device__ float g_h[B_ * OD_];

// ---------------- 128x128x8 SGEMM, 256 threads, 8x8 per thread ---------------
// EPI: 0 = +bias[n], 1 = *scale + logf(cw + 1e-8), 2 = none
// TRANSB: B is [N, Kd] row-major (NT GEMM, used for Q @ K^T)
template <bool TRANSB, int EPI>
__global__ __launch_bounds__(256) void sgemm128(
    const float* __restrict__ A, const float* __restrict__ Bm,
    const float* __restrict__ bias, const float* __restrict__ cw,
    float* __restrict__ C, int M, int Kd, int N,
    long sA, long sB, long sC, float scale)
{
    const int bz = blockIdx.z;
    A  += (long)bz * sA;
    Bm += (long)bz * sB;
    C  += (long)bz * sC;
    const long cwoff = (long)bz * (long)M * (long)N;

    __shared__ float As[8][128];
    __shared__ float Bs[8][128];

    const int tid = threadIdx.x;
    const int tx  = tid & 15;        // 0..15 -> 8 cols each
    const int ty  = tid >> 4;        // 0..15 -> 8 rows each
    const int bm  = blockIdx.x * 128;
    const int bn  = blockIdx.y * 128;
    const int lrow = tid >> 1;              // 0..127
    const int lk4  = (tid & 1) << 2;        // 0 or 4
    const int brow = tid >> 5;              // 0..7
    const int bcol = (tid & 31) << 2;       // 0..124

    float acc[8][8];
#pragma unroll
    for (int i = 0; i < 8; i++)
#pragma unroll
        for (int j = 0; j < 8; j++) acc[i][j] = 0.f;

    for (int k0 = 0; k0 < Kd; k0 += 8) {
        float4 av = *(const float4*)&A[(long)(bm + lrow) * Kd + k0 + lk4];
        As[lk4 + 0][lrow] = av.x;
        As[lk4 + 1][lrow] = av.y;
        As[lk4 + 2][lrow] = av.z;
        As[lk4 + 3][lrow] = av.w;
        if (TRANSB) {
            float4 bv = *(const float4*)&Bm[(long)(bn + lrow) * Kd + k0 + lk4];
            Bs[lk4 + 0][lrow] = bv.x;
            Bs[lk4 + 1][lrow] = bv.y;
            Bs[lk4 + 2][lrow] = bv.z;
            Bs[lk4 + 3][lrow] = bv.w;
        } else {
            *(float4*)&Bs[brow][bcol] =
                *(const float4*)&Bm[(long)(k0 + brow) * N + bn + bcol];
        }
        __syncthreads();
#pragma unroll
        for (int kk = 0; kk < 8; kk++) {
            float a[8], b[8];
            *(float4*)&a[0] = *(const float4*)&As[kk][ty * 8];
            *(float4*)&a[4] = *(const float4*)&As[kk][ty * 8 + 4];
            *(float4*)&b[0] = *(const float4*)&Bs[kk][tx * 8];
            *(float4*)&b[4] = *(const float4*)&Bs[kk][tx * 8 + 4];
#pragma unroll
            for (int i = 0; i < 8; i++)
#pragma unroll
                for (int j = 0; j < 8; j++)
                    acc[i][j] = fmaf(a[i], b[j], acc[i][j]);
        }
        __syncthreads();
    }

#pragma unroll
    for (int i = 0; i < 8; i++) {
        const int m = bm + ty * 8 + i;
#pragma unroll
        for (int j = 0; j < 8; j++) {
            const int n = bn + tx * 8 + j;
            float v = acc[i][j];
            if (EPI == 0) {
                v += bias[n];
            } else if (EPI == 1) {
                v = v * scale + logf(cw[cwoff + (long)m * N + n] + 1e-8f);
            }
            C[(long)m * N + n] = v;
        }
    }
}

// ---------------- row softmax over N=1024, one block per row -----------------
__global__ __launch_bounds__(256) void softmax1024(float* __restrict__ S)
{
    float4* row = (float4*)(S + (long)blockIdx.x * N_);
    const int tid = threadIdx.x;
    float4 v = row[tid];

    float m = fmaxf(fmaxf(v.x, v.y), fmaxf(v.z, v.w));
#pragma unroll
    for (int o = 16; o > 0; o >>= 1)
        m = fmaxf(m, __shfl_xor_sync(0xffffffffu, m, o));
    __shared__ float redm[8];
    if ((tid & 31) == 0) redm[tid >> 5] = m;
    __syncthreads();
    m = fmaxf(fmaxf(fmaxf(redm[0], redm[1]), fmaxf(redm[2], redm[3])),
              fmaxf(fmaxf(redm[4], redm[5]), fmaxf(redm[6], redm[7])));

    v.x = __expf(v.x - m); v.y = __expf(v.y - m);
    v.z = __expf(v.z - m); v.w = __expf(v.w - m);
    float s = v.x + v.y + v.z + v.w;
#pragma unroll
    for (int o = 16; o > 0; o >>= 1)
        s += __shfl_xor_sync(0xffffffffu, s, o);
    __shared__ float reds[8];
    if ((tid & 31) == 0) reds[tid >> 5] = s;
    __syncthreads();
    s = (reds[0] + reds[1]) + (reds[2] + reds[3]) +
        (reds[4] + reds[5]) + (reds[6] + reds[7]);
    const float inv = 1.0f / s;
    v.x *= inv; v.y *= inv; v.z *= inv; v.w *= inv;
    row[tid] = v;
}

// ---------------- mean over N axis: X[B,N,D] -> out[B,D] ---------------------
__global__ __launch_bounds__(128) void pool_mean(const float* __restrict__ X,
                                                 float* __restrict__ out, int D)
{
    const int d = blockIdx.x * 128 + threadIdx.x;
    const float* p = X + (long)blockIdx.y * N_ * D + d;
    float s0 = 0.f, s1 = 0.f, s2 = 0.f, s3 = 0.f;
    for (int n = 0; n < N_; n += 4) {
        s0 += p[(long)(n + 0) * D];
        s1 += p[(long)(n + 1) * D];
        s2 += p[(long)(n + 2) * D];
        s3 += p[(long)(n + 3) * D];
    }
    out[blockIdx.y * D + d] = ((s0 + s1) + (s2 + s3)) * (1.0f / N_);
}

// ---------------- head: concat of two linears --------------------------------
__global__ __launch_bounds__(256) void head_combined(
    const float* __restrict__ cpool, const float* __restrict__ gpool,
    const float* __restrict__ Wcp, const float* __restrict__ bcp,
    const float* __restrict__ Wgp, const float* __restrict__ bgp,
    float* __restrict__ comb)
{
    const int b = blockIdx.y;
    const int o = blockIdx.x * 256 + threadIdx.x;
    float acc;
    if (o < OD_ / 2) {
        const float* a = cpool + b * CD_;
        acc = bcp[o];
        for (int k = 0; k < CD_; k++)
            acc = fmaf(a[k], Wcp[k * (OD_ / 2) + o], acc);
    } else {
        const int oo = o - OD_ / 2;
        const float* a = gpool + b * HD_;
        acc = bgp[oo];
        for (int k = 0; k < HD_; k++)
            acc = fmaf(a[k], Wgp[k * (OD_ / 2) + oo], acc);
    }
    comb[b * OD_ + o] = acc;
}

// ---------------- head: Linear -> BN(eval) -> ReLU ---------------------------
__global__ __launch_bounds__(256) void head_f1(
    const float* __restrict__ comb, const float* __restrict__ W,
    const float* __restrict__ bias, const float* __restrict__ gam,
    const float* __restrict__ bet, const float* __restrict__ mean,
    const float* __restrict__ var, float* __restrict__ h)
{
    __shared__ float sa[OD_];
    const int b = blockIdx.y;
    const int o = blockIdx.x * 256 + threadIdx.x;
    for (int i = threadIdx.x; i < OD_; i += 256) sa[i] = comb[b * OD_ + i];
    __syncthreads();
    float acc = bias[o];
    for (int k = 0; k < OD_; k++)
        acc = fmaf(sa[k], W[(long)k * OD_ + o], acc);
    acc = (acc - mean[o]) * rsqrtf(var[o] + 1e-5f) * gam[o] + bet[o];
    h[b * OD_ + o] = fmaxf(acc, 0.f);
}

// ---------------- head: final Linear -----------------------------------------
__global__ __launch_bounds__(256) void head_f2(
    const float* __restrict__ h, const float* __restrict__ W,
    const float* __restrict__ bias, float* __restrict__ out)
{
    __shared__ float sa[OD_];
    const int b = blockIdx.y;
    const int o = blockIdx.x * 256 + threadIdx.x;
    for (int i = threadIdx.x; i < OD_; i += 256) sa[i] = h[b * OD_ + i];
    __syncthreads();
    float acc = bias[o];
    for (int k = 0; k < OD_; k++)
        acc = fmaf(sa[k], W[(long)k * OD_ + o], acc);
    out[b * OD_ + o] = acc;
}

// -----------------------------------------------------------------------------
extern "C" void kernel_launch(void* const* d_in, const int* in_sizes, int n_in,
                              void* d_out, int out_size)
{
    const float* cf  = (const float*)d_in[0];   // [B,N,CD]
    const float* gf  = (const float*)d_in[1];   // [B,N,GD]
    const float* cw  = (const float*)d_in[2];   // [B,N,N]
    const float* Wq  = (const float*)d_in[3];
    const float* bq  = (const float*)d_in[4];
    const float* Wk  = (const float*)d_in[5];
    const float* bk  = (const float*)d_in[6];
    const float* Wv  = (const float*)d_in[7];
    const float* bv  = (const float*)d_in[8];
    const float* Wcp = (const float*)d_in[9];
    const float* bcp = (const float*)d_in[10];
    const float* Wgp = (const float*)d_in[11];
    const float* bgp = (const float*)d_in[12];
    const float* Wf1 = (const float*)d_in[13];
    const float* bf1 = (const float*)d_in[14];
    const float* bng = (const float*)d_in[15];
    const float* bnb = (const float*)d_in[16];
    const float* bnm = (const float*)d_in[17];
    const float* bnv = (const float*)d_in[18];
    const float* Wf2 = (const float*)d_in[19];
    const float* bf2 = (const float*)d_in[20];

    float* out  = (float*)d_out;            // [B, OD]  = 40960 floats
    float* attn = out + B_ * OD_;           // [B, N, N]

    float *Q, *K, *V, *att, *cp, *gp, *comb, *h;
    cudaGetSymbolAddress((void**)&Q,    g_Q);
    cudaGetSymbolAddress((void**)&K,    g_K);
    cudaGetSymbolAddress((void**)&V,    g_V);
    cudaGetSymbolAddress((void**)&att,  g_att);
    cudaGetSymbolAddress((void**)&cp,   g_cpool);
    cudaGetSymbolAddress((void**)&gp,   g_gpool);
    cudaGetSymbolAddress((void**)&comb, g_comb);
    cudaGetSymbolAddress((void**)&h,    g_h);

    // Projections (flattened over B*N rows)
    sgemm128<false, 0><<<dim3(256, 2, 1), 256>>>(
        cf, Wq, bq, nullptr, Q, B_ * N_, CD_, HD_, 0, 0, 0, 0.f);
    sgemm128<false, 0><<<dim3(256, 2, 1), 256>>>(
        gf, Wk, bk, nullptr, K, B_ * N_, GD_, HD_, 0, 0, 0, 0.f);
    sgemm128<false, 0><<<dim3(256, 2, 1), 256>>>(
        gf, Wv, bv, nullptr, V, B_ * N_, GD_, HD_, 0, 0, 0, 0.f);

    // scores = Q K^T * (1/16) + log(cw + 1e-8)  -> attn region of d_out
    sgemm128<true, 1><<<dim3(8, 8, B_), 256>>>(
        Q, K, nullptr, cw, attn, N_, HD_, N_,
        (long)N_ * HD_, (long)N_ * HD_, (long)N_ * N_, 0.0625f);

    // softmax over last axis, in place
    softmax1024<<<B_ * N_, 256>>>(attn);

    // attended = attn @ V
    sgemm128<false, 2><<<dim3(8, 2, B_), 256>>>(
        attn, V, nullptr, nullptr, att, N_, N_, HD_,
        (long)N_ * N_, (long)N_ * HD_, (long)N_ * HD_, 0.f);

    // pooled means
    pool_mean<<<dim3(CD_ / 128, B_), 128>>>(cf, cp, CD_);
    pool_mean<<<dim3(HD_ / 128, B_), 128>>>(att, gp, HD_);

    // head
    head_combined<<<dim3(OD_ / 256, B_), 256>>>(cp, gp, Wcp, bcp, Wgp, bgp, comb);
    head_f1<<<dim3(OD_ / 256, B_), 256>>>(comb, Wf1, bf1, bng, bnb, bnm, bnv, h);
    head_f2<<<dim3(OD_ / 256, B_), 256>>>(h, Wf2, bf2, out);
}

// round 7
// speedup vs baseline: 1.2675x; 1.2675x over previous
#include <cuda_runtime.h>
#include <math.h>
#include <stdint.h>

#define B_  32
#define N_  1024
#define CD_ 896
#define GD_ 384
#define HD_ 256
#define OD_ 1280

// ---------------- scratch (device globals; no allocation allowed) ------------
__device__ float g_Q[B_ * N_ * HD_];
__device__ float g_K[B_ * N_ * HD_];
__device__ float g_V[B_ * N_ * HD_];
__device__ float g_att[B_ * N_ * HD_];
__device__ float g_cpool[B_ * CD_];
__device__ float g_gpool[B_ * HD_];
__device__ float g_comb[B_ * OD_];
__device__ float g_h[B_ * OD_];

// ---------------- helpers -----------------------------------------------------
__device__ __forceinline__ uint32_t f2tf32(float x) {
    uint32_t r;
    asm("cvt.rna.tf32.f32 %0, %1;" : "=r"(r) : "f"(x));
    return r;
}

__device__ __forceinline__ void split2(float x, uint32_t& hi, uint32_t& lo) {
    hi = f2tf32(x);
    float l = x - __uint_as_float(hi);
    lo = f2tf32(l);
}

__device__ __forceinline__ void mma8(float* d, const uint32_t* a, const uint32_t* b) {
    asm volatile(
        "mma.sync.aligned.m16n8k8.row.col.f32.tf32.tf32.f32 "
        "{%0,%1,%2,%3}, {%4,%5,%6,%7}, {%8,%9}, {%0,%1,%2,%3};\n"
        : "+f"(d[0]), "+f"(d[1]), "+f"(d[2]), "+f"(d[3])
        : "r"(a[0]), "r"(a[1]), "r"(a[2]), "r"(a[3]), "r"(b[0]), "r"(b[1]));
}

__device__ __forceinline__ void cp16(void* s, const void* g) {
    uint32_t sa = (uint32_t)__cvta_generic_to_shared(s);
    asm volatile("cp.async.cg.shared.global [%0], [%1], 16;" :: "r"(sa), "l"(g));
}
#define CP_COMMIT() asm volatile("cp.async.commit_group;")
#define CP_WAIT1()  asm volatile("cp.async.wait_group 1;")
#define CP_WAIT0()  asm volatile("cp.async.wait_group 0;")

// ---------------- TF32x3 tensor-core GEMM, 128x128 tile, KT=16 ----------------
// EPI: 0 = +bias[n], 1 = *scale + logf(cw + 1e-8), 2 = none
// TRANSB: B is [N, Kd] row-major (NT GEMM for Q @ K^T)
template <bool TRANSB, int EPI>
__global__ __launch_bounds__(256, 1) void mma_gemm(
    const float* __restrict__ A, const float* __restrict__ Bm,
    const float* __restrict__ bias, const float* __restrict__ cw,
    float* __restrict__ C, int M, int Kd, int N,
    long sA, long sB, long sC, float scale)
{
    const int bz = blockIdx.z;
    A  += (long)bz * sA;
    Bm += (long)bz * sB;
    C  += (long)bz * sC;
    const long cwoff = (long)bz * (long)M * (long)N;

    // A tile: 128 rows x 16 k, row stride 20 (pad: conflict-free frag loads,
    // 80B rows keep 16B cp.async alignment). B: NN -> [16][132], NT -> [128][20].
    __shared__ float As[2][128][20];
    __shared__ float Bs[2][TRANSB ? (128 * 20) : (16 * 132)];

    const int tid  = threadIdx.x;
    const int lane = tid & 31;
    const int g    = lane >> 2;      // group id 0..7
    const int c    = lane & 3;       // thread-in-group 0..3
    const int w    = tid >> 5;
    const int wm   = (w & 3) * 32;   // warp tile 32(M) x 64(N)
    const int wn   = (w >> 2) * 64;
    const int bm   = blockIdx.x * 128;
    const int bn   = blockIdx.y * 128;

    float acc[2][8][4];
#pragma unroll
    for (int i = 0; i < 2; i++)
#pragma unroll
        for (int j = 0; j < 8; j++)
#pragma unroll
            for (int r = 0; r < 4; r++) acc[i][j][r] = 0.f;

    const int nk = Kd >> 4;

    // stage loader
    auto load_stage = [&](int s, int k0) {
#pragma unroll
        for (int r = 0; r < 2; r++) {
            int ff  = tid + r * 256;        // 0..511 float4s
            int row = ff >> 2;
            int c4  = (ff & 3) << 2;
            cp16(&As[s][row][c4], &A[(long)(bm + row) * Kd + k0 + c4]);
        }
        if (TRANSB) {
#pragma unroll
            for (int r = 0; r < 2; r++) {
                int ff  = tid + r * 256;
                int row = ff >> 2;
                int c4  = (ff & 3) << 2;
                cp16(&Bs[s][row * 20 + c4], &Bm[(long)(bn + row) * Kd + k0 + c4]);
            }
        } else {
#pragma unroll
            for (int r = 0; r < 2; r++) {
                int ff  = tid + r * 256;
                int row = ff >> 5;
                int c4  = (ff & 31) << 2;
                cp16(&Bs[s][row * 132 + c4], &Bm[(long)(k0 + row) * N + bn + c4]);
            }
        }
    };

    load_stage(0, 0);
    CP_COMMIT();

    for (int kt = 0; kt < nk; kt++) {
        if (kt + 1 < nk) {
            load_stage((kt + 1) & 1, (kt + 1) << 4);
            CP_COMMIT();
            CP_WAIT1();
        } else {
            CP_WAIT0();
        }
        __syncthreads();

        const int s = kt & 1;
#pragma unroll
        for (int ks = 0; ks < 2; ks++) {
            const int kb = ks * 8;

            uint32_t ahi[2][4], alo[2][4];
#pragma unroll
            for (int i = 0; i < 2; i++) {
                const int m = wm + i * 16 + g;
                split2(As[s][m    ][kb + c    ], ahi[i][0], alo[i][0]);
                split2(As[s][m + 8][kb + c    ], ahi[i][1], alo[i][1]);
                split2(As[s][m    ][kb + c + 4], ahi[i][2], alo[i][2]);
                split2(As[s][m + 8][kb + c + 4], ahi[i][3], alo[i][3]);
            }

            uint32_t bhi[8][2], blo[8][2];
#pragma unroll
            for (int j = 0; j < 8; j++) {
                const int n = wn + j * 8 + g;
                float b0, b1;
                if (TRANSB) {
                    b0 = Bs[s][n * 20 + kb + c];
                    b1 = Bs[s][n * 20 + kb + c + 4];
                } else {
                    b0 = Bs[s][(kb + c) * 132 + n];
                    b1 = Bs[s][(kb + c + 4) * 132 + n];
                }
                split2(b0, bhi[j][0], blo[j][0]);
                split2(b1, bhi[j][1], blo[j][1]);
            }

#pragma unroll
            for (int i = 0; i < 2; i++)
#pragma unroll
                for (int j = 0; j < 8; j++) {
                    mma8(acc[i][j], ahi[i], bhi[j]);
                    mma8(acc[i][j], alo[i], bhi[j]);
                    mma8(acc[i][j], ahi[i], blo[j]);
                }
        }
        __syncthreads();
    }

    // epilogue
#pragma unroll
    for (int i = 0; i < 2; i++) {
        const int row = bm + wm + i * 16 + g;
#pragma unroll
        for (int j = 0; j < 8; j++) {
            const int col = bn + wn + j * 8 + 2 * c;
            float v0 = acc[i][j][0], v1 = acc[i][j][1];
            float v2 = acc[i][j][2], v3 = acc[i][j][3];
            if (EPI == 0) {
                v0 += bias[col];     v1 += bias[col + 1];
                v2 += bias[col];     v3 += bias[col + 1];
            } else if (EPI == 1) {
                v0 = v0 * scale + logf(cw[cwoff + (long)row * N + col] + 1e-8f);
                v1 = v1 * scale + logf(cw[cwoff + (long)row * N + col + 1] + 1e-8f);
                v2 = v2 * scale + logf(cw[cwoff + (long)(row + 8) * N + col] + 1e-8f);
                v3 = v3 * scale + logf(cw[cwoff + (long)(row + 8) * N + col + 1] + 1e-8f);
            }
            C[(long)row * N + col]           = v0;
            C[(long)row * N + col + 1]       = v1;
            C[(long)(row + 8) * N + col]     = v2;
            C[(long)(row + 8) * N + col + 1] = v3;
        }
    }
}

// ---------------- row softmax over N=1024, one block per row -----------------
__global__ __launch_bounds__(256) void softmax1024(float* __restrict__ S)
{
    float4* row = (float4*)(S + (long)blockIdx.x * N_);
    const int tid = threadIdx.x;
    float4 v = row[tid];

    float m = fmaxf(fmaxf(v.x, v.y), fmaxf(v.z, v.w));
#pragma unroll
    for (int o = 16; o > 0; o >>= 1)
        m = fmaxf(m, __shfl_xor_sync(0xffffffffu, m, o));
    __shared__ float redm[8];
    if ((tid & 31) == 0) redm[tid >> 5] = m;
    __syncthreads();
    m = fmaxf(fmaxf(fmaxf(redm[0], redm[1]), fmaxf(redm[2], redm[3])),
              fmaxf(fmaxf(redm[4], redm[5]), fmaxf(redm[6], redm[7])));

    v.x = __expf(v.x - m); v.y = __expf(v.y - m);
    v.z = __expf(v.z - m); v.w = __expf(v.w - m);
    float s = v.x + v.y + v.z + v.w;
#pragma unroll
    for (int o = 16; o > 0; o >>= 1)
        s += __shfl_xor_sync(0xffffffffu, s, o);
    __shared__ float reds[8];
    if ((tid & 31) == 0) reds[tid >> 5] = s;
    __syncthreads();
    s = (reds[0] + reds[1]) + (reds[2] + reds[3]) +
        (reds[4] + reds[5]) + (reds[6] + reds[7]);
    const float inv = 1.0f / s;
    v.x *= inv; v.y *= inv; v.z *= inv; v.w *= inv;
    row[tid] = v;
}

// ---------------- mean over N axis: X[B,N,D] -> out[B,D] ---------------------
__global__ __launch_bounds__(128) void pool_mean(const float* __restrict__ X,
                                                 float* __restrict__ out, int D)
{
    const int d = blockIdx.x * 128 + threadIdx.x;
    const float* p = X + (long)blockIdx.y * N_ * D + d;
    float s0 = 0.f, s1 = 0.f, s2 = 0.f, s3 = 0.f;
    for (int n = 0; n < N_; n += 4) {
        s0 += p[(long)(n + 0) * D];
        s1 += p[(long)(n + 1) * D];
        s2 += p[(long)(n + 2) * D];
        s3 += p[(long)(n + 3) * D];
    }
    out[blockIdx.y * D + d] = ((s0 + s1) + (s2 + s3)) * (1.0f / N_);
}

// ---------------- head: concat of two linears --------------------------------
__global__ __launch_bounds__(256) void head_combined(
    const float* __restrict__ cpool, const float* __restrict__ gpool,
    const float* __restrict__ Wcp, const float* __restrict__ bcp,
    const float* __restrict__ Wgp, const float* __restrict__ bgp,
    float* __restrict__ comb)
{
    const int b = blockIdx.y;
    const int o = blockIdx.x * 256 + threadIdx.x;
    float acc;
    if (o < OD_ / 2) {
        const float* a = cpool + b * CD_;
        acc = bcp[o];
        for (int k = 0; k < CD_; k++)
            acc = fmaf(a[k], Wcp[k * (OD_ / 2) + o], acc);
    } else {
        const int oo = o - OD_ / 2;
        const float* a = gpool + b * HD_;
        acc = bgp[oo];
        for (int k = 0; k < HD_; k++)
            acc = fmaf(a[k], Wgp[k * (OD_ / 2) + oo], acc);
    }
    comb[b * OD_ + o] = acc;
}

// ---------------- head: Linear -> BN(eval) -> ReLU ---------------------------
__global__ __launch_bounds__(256) void head_f1(
    const float* __restrict__ comb, const float* __restrict__ W,
    const float* __restrict__ bias, const float* __restrict__ gam,
    const float* __restrict__ bet, const float* __restrict__ mean,
    const float* __restrict__ var, float* __restrict__ h)
{
    __shared__ float sa[OD_];
    const int b = blockIdx.y;
    const int o = blockIdx.x * 256 + threadIdx.x;
    for (int i = threadIdx.x; i < OD_; i += 256) sa[i] = comb[b * OD_ + i];
    __syncthreads();
    float acc = bias[o];
    for (int k = 0; k < OD_; k++)
        acc = fmaf(sa[k], W[(long)k * OD_ + o], acc);
    acc = (acc - mean[o]) * rsqrtf(var[o] + 1e-5f) * gam[o] + bet[o];
    h[b * OD_ + o] = fmaxf(acc, 0.f);
}

// ---------------- head: final Linear -----------------------------------------
__global__ __launch_bounds__(256) void head_f2(
    const float* __restrict__ h, const float* __restrict__ W,
    const float* __restrict__ bias, float* __restrict__ out)
{
    __shared__ float sa[OD_];
    const int b = blockIdx.y;
    const int o = blockIdx.x * 256 + threadIdx.x;
    for (int i = threadIdx.x; i < OD_; i += 256) sa[i] = h[b * OD_ + i];
    __syncthreads();
    float acc = bias[o];
    for (int k = 0; k < OD_; k++)
        acc = fmaf(sa[k], W[(long)k * OD_ + o], acc);
    out[b * OD_ + o] = acc;
}

// -----------------------------------------------------------------------------
extern "C" void kernel_launch(void* const* d_in, const int* in_sizes, int n_in,
                              void* d_out, int out_size)
{
    const float* cf  = (const float*)d_in[0];
    const float* gf  = (const float*)d_in[1];
    const float* cw  = (const float*)d_in[2];
    const float* Wq  = (const float*)d_in[3];
    const float* bq  = (const float*)d_in[4];
    const float* Wk  = (const float*)d_in[5];
    const float* bk  = (const float*)d_in[6];
    const float* Wv  = (const float*)d_in[7];
    const float* bv  = (const float*)d_in[8];
    const float* Wcp = (const float*)d_in[9];
    const float* bcp = (const float*)d_in[10];
    const float* Wgp = (const float*)d_in[11];
    const float* bgp = (const float*)d_in[12];
    const float* Wf1 = (const float*)d_in[13];
    const float* bf1 = (const float*)d_in[14];
    const float* bng = (const float*)d_in[15];
    const float* bnb = (const float*)d_in[16];
    const float* bnm = (const float*)d_in[17];
    const float* bnv = (const float*)d_in[18];
    const float* Wf2 = (const float*)d_in[19];
    const float* bf2 = (const float*)d_in[20];

    float* out  = (float*)d_out;            // [B, OD]
    float* attn = out + B_ * OD_;           // [B, N, N]

    float *Q, *K, *V, *att, *cp, *gp, *comb, *h;
    cudaGetSymbolAddress((void**)&Q,    g_Q);
    cudaGetSymbolAddress((void**)&K,    g_K);
    cudaGetSymbolAddress((void**)&V,    g_V);
    cudaGetSymbolAddress((void**)&att,  g_att);
    cudaGetSymbolAddress((void**)&cp,   g_cpool);
    cudaGetSymbolAddress((void**)&gp,   g_gpool);
    cudaGetSymbolAddress((void**)&comb, g_comb);
    cudaGetSymbolAddress((void**)&h,    g_h);

    // Projections (flattened over B*N rows), tensor-core tf32x3
    mma_gemm<false, 0><<<dim3(256, 2, 1), 256>>>(
        cf, Wq, bq, nullptr, Q, B_ * N_, CD_, HD_, 0, 0, 0, 0.f);
    mma_gemm<false, 0><<<dim3(256, 2, 1), 256>>>(
        gf, Wk, bk, nullptr, K, B_ * N_, GD_, HD_, 0, 0, 0, 0.f);
    mma_gemm<false, 0><<<dim3(256, 2, 1), 256>>>(
        gf, Wv, bv, nullptr, V, B_ * N_, GD_, HD_, 0, 0, 0, 0.f);

    // scores = Q K^T * (1/16) + log(cw + 1e-8)  -> attn region of d_out
    mma_gemm<true, 1><<<dim3(8, 8, B_), 256>>>(
        Q, K, nullptr, cw, attn, N_, HD_, N_,
        (long)N_ * HD_, (long)N_ * HD_, (long)N_ * N_, 0.0625f);

    // softmax over last axis, in place
    softmax1024<<<B_ * N_, 256>>>(attn);

    // attended = attn @ V
    mma_gemm<false, 2><<<dim3(8, 2, B_), 256>>>(
        attn, V, nullptr, nullptr, att, N_, N_, HD_,
        (long)N_ * N_, (long)N_ * HD_, (long)N_ * HD_, 0.f);

    // pooled means
    pool_mean<<<dim3(CD_ / 128, B_), 128>>>(cf, cp, CD_);
    pool_mean<<<dim3(HD_ / 128, B_), 128>>>(att, gp, HD_);

    // head
    head_combined<<<dim3(OD_ / 256, B_), 256>>>(cp, gp, Wcp, bcp, Wgp, bgp, comb);
    head_f1<<<dim3(OD_ / 256, B_), 256>>>(comb, Wf1, bf1, bng, bnb, bnm, bnv, h);
    head_f2<<<dim3(OD_ / 256, B_), 256>>>(h, Wf2, bf2, out);
}

// round 8
// speedup vs baseline: 1.5075x; 1.1894x over previous
#include <cuda_runtime.h>
#include <cuda_fp16.h>
#include <math.h>
#include <stdint.h>

#define B_  32
#define N_  1024
#define CD_ 896
#define GD_ 384
#define HD_ 256
#define OD_ 1280

// ---------------- scratch (device globals; no allocation allowed) ------------
__device__ float g_Q[B_ * N_ * HD_];
__device__ float g_K[B_ * N_ * HD_];
__device__ float g_V[B_ * N_ * HD_];
__device__ float g_att[B_ * N_ * HD_];
__device__ float g_cpool[B_ * CD_];
__device__ float g_gpool[B_ * HD_];
__device__ float g_comb[B_ * OD_];
__device__ float g_h[B_ * OD_];

// ---------------- helpers -----------------------------------------------------
// fp16x2 split: x = hi + lo/2048, |x - hi - lo/2048| <~ 2^-22 |x|
__device__ __forceinline__ void split_pair(float x, float y,
                                           uint32_t& hi, uint32_t& lo) {
    __half hx = __float2half_rn(x), hy = __float2half_rn(y);
    float rx = (x - __half2float(hx)) * 2048.0f;
    float ry = (y - __half2float(hy)) * 2048.0f;
    __half2 h2 = __halves2half2(hx, hy);
    __half2 l2 = __floats2half2_rn(rx, ry);
    hi = *reinterpret_cast<uint32_t*>(&h2);
    lo = *reinterpret_cast<uint32_t*>(&l2);
}

__device__ __forceinline__ void mma16(float* d, const uint32_t* a, const uint32_t* b) {
    asm volatile(
        "mma.sync.aligned.m16n8k16.row.col.f32.f16.f16.f32 "
        "{%0,%1,%2,%3}, {%4,%5,%6,%7}, {%8,%9}, {%0,%1,%2,%3};\n"
        : "+f"(d[0]), "+f"(d[1]), "+f"(d[2]), "+f"(d[3])
        : "r"(a[0]), "r"(a[1]), "r"(a[2]), "r"(a[3]), "r"(b[0]), "r"(b[1]));
}

// smem entry offset (in b32 words): 16B entry e of row, XOR swizzled so that
// the consumer pattern (row = base+g, e = c) is bank-conflict-free.
__device__ __forceinline__ int eoff(int row, int e) {
    return row * 16 + ((e ^ (row & 3)) << 2);
}

// ---------------- FP16x2 tensor-core GEMM, 128x128 tile, KT=16 ----------------
// smem entry (row, e) holds {hi2(k=2e,2e+1), lo2(k=2e,2e+1), hi2(k=2e+8,2e+9),
// lo2(k=2e+8,2e+9)} -> exactly one m16n8k16 fragment pair (hi+lo).
// EPI: 0 = +bias[n], 1 = *scale + logf(cw + 1e-8), 2 = none
// TRANSB: B is [N, Kd] row-major (NT GEMM for Q @ K^T)
template <bool TRANSB, int EPI>
__global__ __launch_bounds__(256, 1) void hmma_gemm(
    const float* __restrict__ A, const float* __restrict__ Bm,
    const float* __restrict__ bias, const float* __restrict__ cw,
    float* __restrict__ C, int M, int Kd, int N,
    long sA, long sB, long sC, float scale)
{
    const int bz = blockIdx.z;
    A  += (long)bz * sA;
    Bm += (long)bz * sB;
    C  += (long)bz * sC;
    const long cwoff = (long)bz * (long)M * (long)N;

    __shared__ __align__(16) uint32_t As[2][2048];   // 128 rows x 4 entries x 4 words
    __shared__ __align__(16) uint32_t Bs[2][2048];

    const int tid  = threadIdx.x;
    const int lane = tid & 31;
    const int g    = lane >> 2;       // 0..7
    const int c    = lane & 3;        // 0..3
    const int w    = tid >> 5;
    const int wm   = (w & 3) * 32;    // warp tile 32(M) x 64(N)
    const int wn   = (w >> 2) * 64;
    const int bm   = blockIdx.x * 128;
    const int bn   = blockIdx.y * 128;

    // staging coords
    const int arow = tid >> 1;        // 0..127
    const int ap   = tid & 1;         // which entry pair {0,1} / {2,3}
    const int bnn  = tid & 127;       // NN gather: n within tile

    float accM[2][8][4], accC[2][8][4];
#pragma unroll
    for (int i = 0; i < 2; i++)
#pragma unroll
        for (int j = 0; j < 8; j++)
#pragma unroll
            for (int r = 0; r < 4; r++) { accM[i][j][r] = 0.f; accC[i][j][r] = 0.f; }

    float4 pA0, pA1, pB0, pB1;   // NT prefetch
    float  pb[8];                // NN B prefetch

    auto ldg = [&](int k0) {
        pA0 = *(const float4*)&A[(long)(bm + arow) * Kd + k0 + ap * 4];
        pA1 = *(const float4*)&A[(long)(bm + arow) * Kd + k0 + ap * 4 + 8];
        if (TRANSB) {
            pB0 = *(const float4*)&Bm[(long)(bn + arow) * Kd + k0 + ap * 4];
            pB1 = *(const float4*)&Bm[(long)(bn + arow) * Kd + k0 + ap * 4 + 8];
        } else {
#pragma unroll
            for (int r = 0; r < 2; r++) {
                const int cc = (tid >> 7) + 2 * r;
                const float* p = &Bm[(long)(k0 + 2 * cc) * N + bn + bnn];
                pb[r * 4 + 0] = p[0];
                pb[r * 4 + 1] = p[N];
                pb[r * 4 + 2] = p[(long)8 * N];
                pb[r * 4 + 3] = p[(long)9 * N];
            }
        }
    };

    auto sts = [&](int s) {
        uint32_t h0, l0, h1, l1;
        split_pair(pA0.x, pA0.y, h0, l0); split_pair(pA1.x, pA1.y, h1, l1);
        *(uint4*)&As[s][eoff(arow, 2 * ap)]     = make_uint4(h0, l0, h1, l1);
        split_pair(pA0.z, pA0.w, h0, l0); split_pair(pA1.z, pA1.w, h1, l1);
        *(uint4*)&As[s][eoff(arow, 2 * ap + 1)] = make_uint4(h0, l0, h1, l1);
        if (TRANSB) {
            split_pair(pB0.x, pB0.y, h0, l0); split_pair(pB1.x, pB1.y, h1, l1);
            *(uint4*)&Bs[s][eoff(arow, 2 * ap)]     = make_uint4(h0, l0, h1, l1);
            split_pair(pB0.z, pB0.w, h0, l0); split_pair(pB1.z, pB1.w, h1, l1);
            *(uint4*)&Bs[s][eoff(arow, 2 * ap + 1)] = make_uint4(h0, l0, h1, l1);
        } else {
#pragma unroll
            for (int r = 0; r < 2; r++) {
                const int cc = (tid >> 7) + 2 * r;
                split_pair(pb[r * 4 + 0], pb[r * 4 + 1], h0, l0);
                split_pair(pb[r * 4 + 2], pb[r * 4 + 3], h1, l1);
                *(uint4*)&Bs[s][eoff(bnn, cc)] = make_uint4(h0, l0, h1, l1);
            }
        }
    };

    const int nk = Kd >> 4;
    ldg(0);
    sts(0);
    __syncthreads();

    for (int kt = 0; kt < nk; kt++) {
        if (kt + 1 < nk) ldg((kt + 1) << 4);
        const int s = kt & 1;

        uint4 af[2][2];
#pragma unroll
        for (int i = 0; i < 2; i++) {
            const int r0 = wm + i * 16 + g;
            af[i][0] = *(const uint4*)&As[s][eoff(r0,     c)];
            af[i][1] = *(const uint4*)&As[s][eoff(r0 + 8, c)];
        }
#pragma unroll
        for (int j = 0; j < 8; j++) {
            const int n = wn + j * 8 + g;
            const uint4 bf = *(const uint4*)&Bs[s][eoff(n, c)];
            uint32_t bh[2] = { bf.x, bf.z };
            uint32_t bl[2] = { bf.y, bf.w };
#pragma unroll
            for (int i = 0; i < 2; i++) {
                uint32_t ah[4] = { af[i][0].x, af[i][1].x, af[i][0].z, af[i][1].z };
                uint32_t al[4] = { af[i][0].y, af[i][1].y, af[i][0].w, af[i][1].w };
                mma16(accM[i][j], ah, bh);
                mma16(accC[i][j], al, bh);
                mma16(accC[i][j], ah, bl);
            }
        }

        if (kt + 1 < nk) sts((kt + 1) & 1);
        __syncthreads();
    }

    // epilogue: combine hi/lo accumulators, apply EPI
    const float ilo = 1.0f / 2048.0f;
#pragma unroll
    for (int i = 0; i < 2; i++) {
        const int row = bm + wm + i * 16 + g;
#pragma unroll
        for (int j = 0; j < 8; j++) {
            const int col = bn + wn + j * 8 + 2 * c;
            float v0 = accM[i][j][0] + accC[i][j][0] * ilo;
            float v1 = accM[i][j][1] + accC[i][j][1] * ilo;
            float v2 = accM[i][j][2] + accC[i][j][2] * ilo;
            float v3 = accM[i][j][3] + accC[i][j][3] * ilo;
            if (EPI == 0) {
                v0 += bias[col];     v1 += bias[col + 1];
                v2 += bias[col];     v3 += bias[col + 1];
            } else if (EPI == 1) {
                v0 = v0 * scale + logf(cw[cwoff + (long)row * N + col] + 1e-8f);
                v1 = v1 * scale + logf(cw[cwoff + (long)row * N + col + 1] + 1e-8f);
                v2 = v2 * scale + logf(cw[cwoff + (long)(row + 8) * N + col] + 1e-8f);
                v3 = v3 * scale + logf(cw[cwoff + (long)(row + 8) * N + col + 1] + 1e-8f);
            }
            C[(long)row * N + col]           = v0;
            C[(long)row * N + col + 1]       = v1;
            C[(long)(row + 8) * N + col]     = v2;
            C[(long)(row + 8) * N + col + 1] = v3;
        }
    }
}

// ---------------- row softmax over N=1024, one block per row -----------------
__global__ __launch_bounds__(256) void softmax1024(float* __restrict__ S)
{
    float4* row = (float4*)(S + (long)blockIdx.x * N_);
    const int tid = threadIdx.x;
    float4 v = row[tid];

    float m = fmaxf(fmaxf(v.x, v.y), fmaxf(v.z, v.w));
#pragma unroll
    for (int o = 16; o > 0; o >>= 1)
        m = fmaxf(m, __shfl_xor_sync(0xffffffffu, m, o));
    __shared__ float redm[8];
    if ((tid & 31) == 0) redm[tid >> 5] = m;
    __syncthreads();
    m = fmaxf(fmaxf(fmaxf(redm[0], redm[1]), fmaxf(redm[2], redm[3])),
              fmaxf(fmaxf(redm[4], redm[5]), fmaxf(redm[6], redm[7])));

    v.x = __expf(v.x - m); v.y = __expf(v.y - m);
    v.z = __expf(v.z - m); v.w = __expf(v.w - m);
    float s = v.x + v.y + v.z + v.w;
#pragma unroll
    for (int o = 16; o > 0; o >>= 1)
        s += __shfl_xor_sync(0xffffffffu, s, o);
    __shared__ float reds[8];
    if ((tid & 31) == 0) reds[tid >> 5] = s;
    __syncthreads();
    s = (reds[0] + reds[1]) + (reds[2] + reds[3]) +
        (reds[4] + reds[5]) + (reds[6] + reds[7]);
    const float inv = 1.0f / s;
    v.x *= inv; v.y *= inv; v.z *= inv; v.w *= inv;
    row[tid] = v;
}

// ---------------- mean over N axis: X[B,N,D] -> out[B,D] ---------------------
__global__ __launch_bounds__(128) void pool_mean(const float* __restrict__ X,
                                                 float* __restrict__ out, int D)
{
    const int d = blockIdx.x * 128 + threadIdx.x;
    const float* p = X + (long)blockIdx.y * N_ * D + d;
    float s0 = 0.f, s1 = 0.f, s2 = 0.f, s3 = 0.f;
    for (int n = 0; n < N_; n += 4) {
        s0 += p[(long)(n + 0) * D];
        s1 += p[(long)(n + 1) * D];
        s2 += p[(long)(n + 2) * D];
        s3 += p[(long)(n + 3) * D];
    }
    out[blockIdx.y * D + d] = ((s0 + s1) + (s2 + s3)) * (1.0f / N_);
}

// ---------------- head: concat of two linears --------------------------------
__global__ __launch_bounds__(256) void head_combined(
    const float* __restrict__ cpool, const float* __restrict__ gpool,
    const float* __restrict__ Wcp, const float* __restrict__ bcp,
    const float* __restrict__ Wgp, const float* __restrict__ bgp,
    float* __restrict__ comb)
{
    const int b = blockIdx.y;
    const int o = blockIdx.x * 256 + threadIdx.x;
    float acc;
    if (o < OD_ / 2) {
        const float* a = cpool + b * CD_;
        acc = bcp[o];
        for (int k = 0; k < CD_; k++)
            acc = fmaf(a[k], Wcp[k * (OD_ / 2) + o], acc);
    } else {
        const int oo = o - OD_ / 2;
        const float* a = gpool + b * HD_;
        acc = bgp[oo];
        for (int k = 0; k < HD_; k++)
            acc = fmaf(a[k], Wgp[k * (OD_ / 2) + oo], acc);
    }
    comb[b * OD_ + o] = acc;
}

// ---------------- head: Linear -> BN(eval) -> ReLU ---------------------------
__global__ __launch_bounds__(256) void head_f1(
    const float* __restrict__ comb, const float* __restrict__ W,
    const float* __restrict__ bias, const float* __restrict__ gam,
    const float* __restrict__ bet, const float* __restrict__ mean,
    const float* __restrict__ var, float* __restrict__ h)
{
    __shared__ float sa[OD_];
    const int b = blockIdx.y;
    const int o = blockIdx.x * 256 + threadIdx.x;
    for (int i = threadIdx.x; i < OD_; i += 256) sa[i] = comb[b * OD_ + i];
    __syncthreads();
    float acc = bias[o];
    for (int k = 0; k < OD_; k++)
        acc = fmaf(sa[k], W[(long)k * OD_ + o], acc);
    acc = (acc - mean[o]) * rsqrtf(var[o] + 1e-5f) * gam[o] + bet[o];
    h[b * OD_ + o] = fmaxf(acc, 0.f);
}

// ---------------- head: final Linear -----------------------------------------
__global__ __launch_bounds__(256) void head_f2(
    const float* __restrict__ h, const float* __restrict__ W,
    const float* __restrict__ bias, float* __restrict__ out)
{
    __shared__ float sa[OD_];
    const int b = blockIdx.y;
    const int o = blockIdx.x * 256 + threadIdx.x;
    for (int i = threadIdx.x; i < OD_; i += 256) sa[i] = h[b * OD_ + i];
    __syncthreads();
    float acc = bias[o];
    for (int k = 0; k < OD_; k++)
        acc = fmaf(sa[k], W[(long)k * OD_ + o], acc);
    out[b * OD_ + o] = acc;
}

// -----------------------------------------------------------------------------
extern "C" void kernel_launch(void* const* d_in, const int* in_sizes, int n_in,
                              void* d_out, int out_size)
{
    const float* cf  = (const float*)d_in[0];
    const float* gf  = (const float*)d_in[1];
    const float* cw  = (const float*)d_in[2];
    const float* Wq  = (const float*)d_in[3];
    const float* bq  = (const float*)d_in[4];
    const float* Wk  = (const float*)d_in[5];
    const float* bk  = (const float*)d_in[6];
    const float* Wv  = (const float*)d_in[7];
    const float* bv  = (const float*)d_in[8];
    const float* Wcp = (const float*)d_in[9];
    const float* bcp = (const float*)d_in[10];
    const float* Wgp = (const float*)d_in[11];
    const float* bgp = (const float*)d_in[12];
    const float* Wf1 = (const float*)d_in[13];
    const float* bf1 = (const float*)d_in[14];
    const float* bng = (const float*)d_in[15];
    const float* bnb = (const float*)d_in[16];
    const float* bnm = (const float*)d_in[17];
    const float* bnv = (const float*)d_in[18];
    const float* Wf2 = (const float*)d_in[19];
    const float* bf2 = (const float*)d_in[20];

    float* out  = (float*)d_out;            // [B, OD]
    float* attn = out + B_ * OD_;           // [B, N, N]

    float *Q, *K, *V, *att, *cp, *gp, *comb, *h;
    cudaGetSymbolAddress((void**)&Q,    g_Q);
    cudaGetSymbolAddress((void**)&K,    g_K);
    cudaGetSymbolAddress((void**)&V,    g_V);
    cudaGetSymbolAddress((void**)&att,  g_att);
    cudaGetSymbolAddress((void**)&cp,   g_cpool);
    cudaGetSymbolAddress((void**)&gp,   g_gpool);
    cudaGetSymbolAddress((void**)&comb, g_comb);
    cudaGetSymbolAddress((void**)&h,    g_h);

    // Projections (flattened over B*N rows), tensor-core fp16x2
    hmma_gemm<false, 0><<<dim3(256, 2, 1), 256>>>(
        cf, Wq, bq, nullptr, Q, B_ * N_, CD_, HD_, 0, 0, 0, 0.f);
    hmma_gemm<false, 0><<<dim3(256, 2, 1), 256>>>(
        gf, Wk, bk, nullptr, K, B_ * N_, GD_, HD_, 0, 0, 0, 0.f);
    hmma_gemm<false, 0><<<dim3(256, 2, 1), 256>>>(
        gf, Wv, bv, nullptr, V, B_ * N_, GD_, HD_, 0, 0, 0, 0.f);

    // scores = Q K^T * (1/16) + log(cw + 1e-8)  -> attn region of d_out
    hmma_gemm<true, 1><<<dim3(8, 8, B_), 256>>>(
        Q, K, nullptr, cw, attn, N_, HD_, N_,
        (long)N_ * HD_, (long)N_ * HD_, (long)N_ * N_, 0.0625f);

    // softmax over last axis, in place
    softmax1024<<<B_ * N_, 256>>>(attn);

    // attended = attn @ V
    hmma_gemm<false, 2><<<dim3(8, 2, B_), 256>>>(
        attn, V, nullptr, nullptr, att, N_, N_, HD_,
        (long)N_ * N_, (long)N_ * HD_, (long)N_ * HD_, 0.f);

    // pooled means
    pool_mean<<<dim3(CD_ / 128, B_), 128>>>(cf, cp, CD_);
    pool_mean<<<dim3(HD_ / 128, B_), 128>>>(att, gp, HD_);

    // head
    head_combined<<<dim3(OD_ / 256, B_), 256>>>(cp, gp, Wcp, bcp, Wgp, bgp, comb);
    head_f1<<<dim3(OD_ / 256, B_), 256>>>(comb, Wf1, bf1, bng, bnb, bnm, bnv, h);
    head_f2<<<dim3(OD_ / 256, B_), 256>>>(h, Wf2, bf2, out);
}